// round 1
// baseline (speedup 1.0000x reference)
#include <cuda_runtime.h>

#define BB   4
#define SS   2048
#define DD   1024
#define DQKC 128
#define DVC  256
#define MM   (BB * SS)   // 8192

// Scratch (device globals — no allocation allowed)
__device__ float g_Q[MM * DQKC];
__device__ float g_K[MM * DQKC];
__device__ float g_V[MM * DVC];
__device__ float g_G[MM * DVC];
__device__ float g_AV[MM * DVC];

// ---------------------------------------------------------------------------
// Kernel 1: fused QKVG projections.  Y = X @ W + b
// BM=128, BN=128, BK=16, 256 threads, 8x8 microtile.
// blockIdx.y selects (weight, 128-col slab): 0:Q 1:K 2:V[0:128] 3:V[128:256]
//                                            4:G[0:128] 5:G[128:256]
// ---------------------------------------------------------------------------
__global__ __launch_bounds__(256) void proj_kernel(
    const float* __restrict__ X,
    const float* __restrict__ Wq, const float* __restrict__ bq,
    const float* __restrict__ Wk, const float* __restrict__ bk,
    const float* __restrict__ Wv, const float* __restrict__ bv,
    const float* __restrict__ Wg, const float* __restrict__ bg)
{
    __shared__ float Xs[16][132];   // transposed: Xs[k][m]
    __shared__ float Ws[16][132];   // Ws[k][n]

    const float* W; const float* bias; float* out; int N; int n0;
    switch (blockIdx.y) {
        case 0:  W = Wq; bias = bq; out = g_Q; N = DQKC; n0 = 0;   break;
        case 1:  W = Wk; bias = bk; out = g_K; N = DQKC; n0 = 0;   break;
        case 2:  W = Wv; bias = bv; out = g_V; N = DVC;  n0 = 0;   break;
        case 3:  W = Wv; bias = bv; out = g_V; N = DVC;  n0 = 128; break;
        case 4:  W = Wg; bias = bg; out = g_G; N = DVC;  n0 = 0;   break;
        default: W = Wg; bias = bg; out = g_G; N = DVC;  n0 = 128; break;
    }
    const int m0  = blockIdx.x * 128;
    const int tid = threadIdx.x;
    const int tx  = tid & 15;     // col tile 0..15
    const int ty  = tid >> 4;     // row tile 0..15

    const int lm = tid >> 2;            // 0..63  (X-tile row, 2 passes)
    const int lk = (tid & 3) * 4;       // 0,4,8,12
    const int wr = tid >> 5;            // 0..7   (W-tile row, 2 passes)
    const int wc = (tid & 31) * 4;      // 0..124

    float acc[8][8] = {};

    for (int k0 = 0; k0 < DD; k0 += 16) {
        #pragma unroll
        for (int p = 0; p < 2; p++) {
            int m = lm + p * 64;
            float4 v = *(const float4*)&X[(m0 + m) * DD + k0 + lk];
            Xs[lk + 0][m] = v.x;
            Xs[lk + 1][m] = v.y;
            Xs[lk + 2][m] = v.z;
            Xs[lk + 3][m] = v.w;
        }
        #pragma unroll
        for (int p = 0; p < 2; p++) {
            int r = wr + p * 8;
            *(float4*)&Ws[r][wc] = *(const float4*)&W[(k0 + r) * N + n0 + wc];
        }
        __syncthreads();
        #pragma unroll
        for (int kk = 0; kk < 16; kk++) {
            float a[8], b[8];
            *(float4*)&a[0] = *(float4*)&Xs[kk][ty * 8];
            *(float4*)&a[4] = *(float4*)&Xs[kk][ty * 8 + 4];
            *(float4*)&b[0] = *(float4*)&Ws[kk][tx * 8];
            *(float4*)&b[4] = *(float4*)&Ws[kk][tx * 8 + 4];
            #pragma unroll
            for (int i = 0; i < 8; i++)
                #pragma unroll
                for (int j = 0; j < 8; j++)
                    acc[i][j] = fmaf(a[i], b[j], acc[i][j]);
        }
        __syncthreads();
    }

    float bv8[8];
    #pragma unroll
    for (int j = 0; j < 8; j++) bv8[j] = bias[n0 + tx * 8 + j];
    #pragma unroll
    for (int i = 0; i < 8; i++) {
        int m = m0 + ty * 8 + i;
        #pragma unroll
        for (int j = 0; j < 8; j++) acc[i][j] += bv8[j];
        *(float4*)&out[m * N + n0 + tx * 8]     = *(float4*)&acc[i][0];
        *(float4*)&out[m * N + n0 + tx * 8 + 4] = *(float4*)&acc[i][4];
    }
}

// ---------------------------------------------------------------------------
// Kernel 2: Shepard attention, flash-style streaming.
// One block per (batch, 64-row q-tile). 256 threads.
// Per 64-key chunk: s = Q@K^T (4x4 microtile), w = 1/max(d2,1e-16),
// acc[64,256] += w @ V (8x8 microtile). Normalize by row-sum at the end.
// ---------------------------------------------------------------------------
#define QS_STRIDE 68
#define ATT_SMEM_FLOATS (128*QS_STRIDE + 128*QS_STRIDE + 64*256 + 64*QS_STRIDE + 64 + 64 + 64 + 256)
#define ATT_SMEM_BYTES  (ATT_SMEM_FLOATS * 4)

__global__ __launch_bounds__(256) void attn_kernel()
{
    extern __shared__ float sm[];
    float* QsT  = sm;                          // [128][68]  QsT[k][q]
    float* KsT  = QsT + 128 * QS_STRIDE;       // [128][68]  KsT[k][c]
    float* Vs   = KsT + 128 * QS_STRIDE;       // [64][256]
    float* wT   = Vs  + 64 * 256;              // [64][68]   wT[key][q]
    float* q2   = wT  + 64 * QS_STRIDE;        // [64]
    float* k2   = q2  + 64;                    // [64]
    float* wsum = k2  + 64;                    // [64]
    float* red  = wsum + 64;                   // [256]

    const int tid   = threadIdx.x;
    const int b     = blockIdx.x >> 5;
    const int qt    = blockIdx.x & 31;
    const int qrow0 = b * SS + qt * 64;
    const int krow0 = b * SS;

    // Load Q tile transposed
    for (int i = tid; i < 64 * 32; i += 256) {
        int r = i & 63, kg = i >> 6;
        float4 v = *(const float4*)&g_Q[(qrow0 + r) * DQKC + kg * 4];
        QsT[(kg * 4 + 0) * QS_STRIDE + r] = v.x;
        QsT[(kg * 4 + 1) * QS_STRIDE + r] = v.y;
        QsT[(kg * 4 + 2) * QS_STRIDE + r] = v.z;
        QsT[(kg * 4 + 3) * QS_STRIDE + r] = v.w;
    }
    if (tid < 64) wsum[tid] = 0.0f;
    __syncthreads();

    // q2[r] = sum_k Q[r][k]^2 (4-way split reduce)
    {
        int c = tid & 63, part = tid >> 6;
        float s = 0.0f;
        for (int k = part * 32; k < part * 32 + 32; k++) {
            float v = QsT[k * QS_STRIDE + c];
            s = fmaf(v, v, s);
        }
        red[part * 64 + c] = s;
    }
    __syncthreads();
    if (tid < 64) q2[tid] = red[tid] + red[64 + tid] + red[128 + tid] + red[192 + tid];
    // (ordered before first use by the sync inside the chunk loop)

    float acc[8][8] = {};   // w@V accumulator

    const int r0p1 = (tid >> 4) * 4, c0p1 = (tid & 15) * 4;   // phase-1 microtile
    const int r0p2 = (tid >> 5) * 8, c0p2 = (tid & 31) * 8;   // phase-2 microtile

    for (int kc = 0; kc < 32; kc++) {
        const int kbase = krow0 + kc * 64;
        // Load K chunk transposed
        for (int i = tid; i < 64 * 32; i += 256) {
            int r = i & 63, kg = i >> 6;
            float4 v = *(const float4*)&g_K[(kbase + r) * DQKC + kg * 4];
            KsT[(kg * 4 + 0) * QS_STRIDE + r] = v.x;
            KsT[(kg * 4 + 1) * QS_STRIDE + r] = v.y;
            KsT[(kg * 4 + 2) * QS_STRIDE + r] = v.z;
            KsT[(kg * 4 + 3) * QS_STRIDE + r] = v.w;
        }
        // Load V chunk (row-major)
        for (int i = tid; i < 64 * 64; i += 256) {
            int r = i >> 6, cg = i & 63;
            *(float4*)&Vs[r * 256 + cg * 4] =
                *(const float4*)&g_V[(kbase + r) * DVC + cg * 4];
        }
        __syncthreads();

        // k2 for this chunk
        {
            int c = tid & 63, part = tid >> 6;
            float s = 0.0f;
            for (int k = part * 32; k < part * 32 + 32; k++) {
                float v = KsT[k * QS_STRIDE + c];
                s = fmaf(v, v, s);
            }
            red[part * 64 + c] = s;
        }
        __syncthreads();
        if (tid < 64) k2[tid] = red[tid] + red[64 + tid] + red[128 + tid] + red[192 + tid];
        __syncthreads();

        // Phase 1: s = Q @ K^T, then w = 1/max(d2, 1e-16), stored transposed
        {
            float sacc[4][4] = {};
            #pragma unroll 4
            for (int kk = 0; kk < 128; kk++) {
                float4 qv = *(float4*)&QsT[kk * QS_STRIDE + r0p1];
                float4 kv = *(float4*)&KsT[kk * QS_STRIDE + c0p1];
                float qa[4] = {qv.x, qv.y, qv.z, qv.w};
                float ka[4] = {kv.x, kv.y, kv.z, kv.w};
                #pragma unroll
                for (int i = 0; i < 4; i++)
                    #pragma unroll
                    for (int j = 0; j < 4; j++)
                        sacc[i][j] = fmaf(qa[i], ka[j], sacc[i][j]);
            }
            float q2l[4], k2l[4], rsum[4] = {};
            #pragma unroll
            for (int i = 0; i < 4; i++) q2l[i] = q2[r0p1 + i];
            #pragma unroll
            for (int j = 0; j < 4; j++) k2l[j] = k2[c0p1 + j];
            #pragma unroll
            for (int i = 0; i < 4; i++) {
                #pragma unroll
                for (int j = 0; j < 4; j++) {
                    float d2 = q2l[i] + k2l[j] - 2.0f * sacc[i][j];
                    d2 = fmaxf(d2, 0.0f);
                    float w = 1.0f / fmaxf(d2, 1e-16f);
                    wT[(c0p1 + j) * QS_STRIDE + (r0p1 + i)] = w;
                    rsum[i] += w;
                }
            }
            #pragma unroll
            for (int i = 0; i < 4; i++) atomicAdd(&wsum[r0p1 + i], rsum[i]);
        }
        __syncthreads();

        // Phase 2: acc += w @ V
        #pragma unroll 4
        for (int kk = 0; kk < 64; kk++) {
            float w[8], v[8];
            *(float4*)&w[0] = *(float4*)&wT[kk * QS_STRIDE + r0p2];
            *(float4*)&w[4] = *(float4*)&wT[kk * QS_STRIDE + r0p2 + 4];
            *(float4*)&v[0] = *(float4*)&Vs[kk * 256 + c0p2];
            *(float4*)&v[4] = *(float4*)&Vs[kk * 256 + c0p2 + 4];
            #pragma unroll
            for (int i = 0; i < 8; i++)
                #pragma unroll
                for (int j = 0; j < 8; j++)
                    acc[i][j] = fmaf(w[i], v[j], acc[i][j]);
        }
        __syncthreads();
    }

    // Normalize and store
    float inv[8];
    #pragma unroll
    for (int i = 0; i < 8; i++) inv[i] = 1.0f / wsum[r0p2 + i];
    #pragma unroll
    for (int i = 0; i < 8; i++) {
        int m = qrow0 + r0p2 + i;
        #pragma unroll
        for (int j = 0; j < 8; j++) acc[i][j] *= inv[i];
        *(float4*)&g_AV[m * DVC + c0p2]     = *(float4*)&acc[i][0];
        *(float4*)&g_AV[m * DVC + c0p2 + 4] = *(float4*)&acc[i][4];
    }
}

// ---------------------------------------------------------------------------
// Kernel 3: out = X + (AV .* G) @ Wp + bp
// BM=128, BN=128, BK=16, 256 threads, 8x8 microtile. Gate fused on A-load.
// ---------------------------------------------------------------------------
__global__ __launch_bounds__(256) void out_kernel(
    const float* __restrict__ X,
    const float* __restrict__ Wp, const float* __restrict__ bp,
    float* __restrict__ out)
{
    __shared__ float As[16][132];   // transposed: As[k][m]
    __shared__ float Bs[16][132];

    const int m0  = blockIdx.x * 128;
    const int n0  = blockIdx.y * 128;
    const int tid = threadIdx.x;
    const int tx  = tid & 15, ty = tid >> 4;
    const int lm  = tid >> 2, lk = (tid & 3) * 4;
    const int wr  = tid >> 5, wc = (tid & 31) * 4;

    float acc[8][8] = {};

    for (int k0 = 0; k0 < DVC; k0 += 16) {
        #pragma unroll
        for (int p = 0; p < 2; p++) {
            int m = lm + p * 64;
            float4 a = *(const float4*)&g_AV[(m0 + m) * DVC + k0 + lk];
            float4 g = *(const float4*)&g_G[(m0 + m) * DVC + k0 + lk];
            As[lk + 0][m] = a.x * g.x;
            As[lk + 1][m] = a.y * g.y;
            As[lk + 2][m] = a.z * g.z;
            As[lk + 3][m] = a.w * g.w;
        }
        #pragma unroll
        for (int p = 0; p < 2; p++) {
            int r = wr + p * 8;
            *(float4*)&Bs[r][wc] = *(const float4*)&Wp[(k0 + r) * DD + n0 + wc];
        }
        __syncthreads();
        #pragma unroll
        for (int kk = 0; kk < 16; kk++) {
            float a[8], b[8];
            *(float4*)&a[0] = *(float4*)&As[kk][ty * 8];
            *(float4*)&a[4] = *(float4*)&As[kk][ty * 8 + 4];
            *(float4*)&b[0] = *(float4*)&Bs[kk][tx * 8];
            *(float4*)&b[4] = *(float4*)&Bs[kk][tx * 8 + 4];
            #pragma unroll
            for (int i = 0; i < 8; i++)
                #pragma unroll
                for (int j = 0; j < 8; j++)
                    acc[i][j] = fmaf(a[i], b[j], acc[i][j]);
        }
        __syncthreads();
    }

    float bv8[8];
    #pragma unroll
    for (int j = 0; j < 8; j++) bv8[j] = bp[n0 + tx * 8 + j];
    #pragma unroll
    for (int i = 0; i < 8; i++) {
        int m = m0 + ty * 8 + i;
        float4 x0 = *(const float4*)&X[m * DD + n0 + tx * 8];
        float4 x1 = *(const float4*)&X[m * DD + n0 + tx * 8 + 4];
        acc[i][0] += bv8[0] + x0.x;  acc[i][1] += bv8[1] + x0.y;
        acc[i][2] += bv8[2] + x0.z;  acc[i][3] += bv8[3] + x0.w;
        acc[i][4] += bv8[4] + x1.x;  acc[i][5] += bv8[5] + x1.y;
        acc[i][6] += bv8[6] + x1.z;  acc[i][7] += bv8[7] + x1.w;
        *(float4*)&out[m * DD + n0 + tx * 8]     = *(float4*)&acc[i][0];
        *(float4*)&out[m * DD + n0 + tx * 8 + 4] = *(float4*)&acc[i][4];
    }
}

// ---------------------------------------------------------------------------
extern "C" void kernel_launch(void* const* d_in, const int* in_sizes, int n_in,
                              void* d_out, int out_size)
{
    const float* X  = (const float*)d_in[0];
    const float* Wq = (const float*)d_in[1];
    const float* bq = (const float*)d_in[2];
    const float* Wk = (const float*)d_in[3];
    const float* bk = (const float*)d_in[4];
    const float* Wv = (const float*)d_in[5];
    const float* bv = (const float*)d_in[6];
    const float* Wg = (const float*)d_in[7];
    const float* bg = (const float*)d_in[8];
    const float* Wp = (const float*)d_in[9];
    const float* bp = (const float*)d_in[10];
    float* out = (float*)d_out;

    cudaFuncSetAttribute(attn_kernel,
                         cudaFuncAttributeMaxDynamicSharedMemorySize,
                         ATT_SMEM_BYTES);

    proj_kernel<<<dim3(64, 6), 256>>>(X, Wq, bq, Wk, bk, Wv, bv, Wg, bg);
    attn_kernel<<<128, 256, ATT_SMEM_BYTES>>>();
    out_kernel<<<dim3(64, 8), 256>>>(X, Wp, bp, out);
}